// round 14
// baseline (speedup 1.0000x reference)
#include <cuda_runtime.h>
#include <cstdint>
#include <cstddef>

// ---------------------------------------------------------------------------
// MultiheadAttention (equivariant graph attention), fp32, round 14.
// N=50000 nodes, E=800000 edges, D_IN=128, SH=16, EA=16, H=8, DQ=DK=64, DV=128
//
// R14 vs R13 (1768; best 1755; edgek 639 stable, edgev ~990 at 2 CTAs):
//  * edgev: acc/rv lifetimes made disjoint -> 3 CTAs without recompute:
//      big GEMM acc -> sync -> spill acc into dead G (8 STS) ->
//      rv = H @ W2v (acc regs recycled) -> read V back (same thread, no
//      sync) -> scale+scatter.  Peak live regs ~80 -> launch_bounds(256,3),
//      no local spills, smem 60.5KB -> 3 CTAs.
//    Cost: +16 L1 ops/thread + 1 barrier (vs R12's failed +128 ops+1024 FMA).
//  * edgek unchanged from R13 (639us).
// ---------------------------------------------------------------------------

#define NMAX 50000
#define EMAX 800000

__device__ float g_q2[NMAX * 64];
__device__ float g_Wq2[128 * 64];
__device__ float g_WangkT[16 * 128];
__device__ float g_WangvT[16 * 128];
__device__ float g_denom[NMAX * 8];
__device__ float g_numer[NMAX * 128];
__device__ float g_ealpha[EMAX * 8];
__device__ int   g_eidx[2 * EMAX];

__device__ __forceinline__ void red_add_v4(float* p, float4 v) {
    asm volatile("red.global.add.v4.f32 [%0], {%1,%2,%3,%4};"
                 :: "l"(p), "f"(v.x), "f"(v.y), "f"(v.z), "f"(v.w)
                 : "memory");
}

// Edge-kernel map: 256 threads -> 16 ty x 16 tx; warp = 8 ty x 4 tx.
// lane bit0 == tx bit0 (alpha shfl pairing). Rows owned: r = 16*i + ty.
__device__ __forceinline__ void thread_mapE(int t, int& ty, int& tx) {
    const int lane = t & 31, w = t >> 5;
    tx = ((w & 3) << 2) | (lane & 3);
    ty = ((w >> 2) << 3) | (lane >> 2);
}

// ---------------------------------------------------------------------------
// Index dtype detection + normalization (int32 or int64 input).
// ---------------------------------------------------------------------------
__global__ void convert_idx_kernel(const void* __restrict__ p, int twoE) {
    const int* pi = (const int*)p;
    int w = 2 * (int)threadIdx.x + 1;
    int nz = (w < twoE) ? (pi[w] != 0) : 0;
    __shared__ int any;
    if (threadIdx.x == 0) any = 0;
    __syncthreads();
    if (nz) any = 1;
    __syncthreads();
    const bool is64 = (any == 0);
    const int i = blockIdx.x * blockDim.x + threadIdx.x;
    if (i < twoE) {
        long long v = is64 ? __ldg((const long long*)p + i)
                           : (long long)__ldg((const int*)p + i);
        g_eidx[i] = (int)v;
    }
}

// ---------------------------------------------------------------------------
// Edge GEMM core (interleaved rows r=16i+ty): C[64,16*CPT] = A[64,KD]@B
// A in smem, LDA must be 4*odd mod 32 (20/68/132). B via __ldg, 64B/warp.
// ---------------------------------------------------------------------------
template <int KD, int LDA, int CPT>
__device__ __forceinline__ void gemmE(const float* __restrict__ As,
                                      const float* __restrict__ Bg,
                                      float (&acc)[4][CPT], int ty, int tx) {
    constexpr int NO = 16 * CPT;
#pragma unroll
    for (int i = 0; i < 4; i++)
#pragma unroll
        for (int j = 0; j < CPT; j++) acc[i][j] = 0.f;

#pragma unroll
    for (int d = 0; d < KD; d += 4) {
        float a[4][4];
#pragma unroll
        for (int i = 0; i < 4; i++)
            *(float4*)&a[i][0] = *(const float4*)(As + (16 * i + ty) * LDA + d);
#pragma unroll
        for (int dd = 0; dd < 4; ++dd) {
            const float4* B4 = reinterpret_cast<const float4*>(Bg + (size_t)(d + dd) * NO);
            float4 b0 = __ldg(B4 + tx);
#pragma unroll
            for (int i = 0; i < 4; i++) {
                acc[i][0] = fmaf(a[i][dd], b0.x, acc[i][0]);
                acc[i][1] = fmaf(a[i][dd], b0.y, acc[i][1]);
                acc[i][2] = fmaf(a[i][dd], b0.z, acc[i][2]);
                acc[i][3] = fmaf(a[i][dd], b0.w, acc[i][3]);
            }
            if (CPT == 8) {
                float4 b1 = __ldg(B4 + 16 + tx);
#pragma unroll
                for (int i = 0; i < 4; i++) {
                    acc[i][4] = fmaf(a[i][dd], b1.x, acc[i][4]);
                    acc[i][5] = fmaf(a[i][dd], b1.y, acc[i][5]);
                    acc[i][6] = fmaf(a[i][dd], b1.z, acc[i][6]);
                    acc[i][7] = fmaf(a[i][dd], b1.w, acc[i][7]);
                }
            }
        }
    }
}

// R6-style core for q2/out kernels (rows 4ty+i, ty = t>>4).
template <int KD, int LDA, int CPT>
__device__ __forceinline__ void gemm_core(const float* __restrict__ As,
                                          const float* __restrict__ Bg,
                                          float (&acc)[4][CPT], int ty, int tx) {
    constexpr int NO = 16 * CPT;
#pragma unroll
    for (int i = 0; i < 4; i++)
#pragma unroll
        for (int j = 0; j < CPT; j++) acc[i][j] = 0.f;

#pragma unroll
    for (int d = 0; d < KD; d += 4) {
        float a[4][4];
#pragma unroll
        for (int i = 0; i < 4; i++)
            *(float4*)&a[i][0] = *(const float4*)(As + (4 * ty + i) * LDA + d);
#pragma unroll
        for (int dd = 0; dd < 4; ++dd) {
            const float4* B4 = reinterpret_cast<const float4*>(Bg + (size_t)(d + dd) * NO);
            float4 b0 = __ldg(B4 + tx);
#pragma unroll
            for (int i = 0; i < 4; i++) {
                acc[i][0] = fmaf(a[i][dd], b0.x, acc[i][0]);
                acc[i][1] = fmaf(a[i][dd], b0.y, acc[i][1]);
                acc[i][2] = fmaf(a[i][dd], b0.z, acc[i][2]);
                acc[i][3] = fmaf(a[i][dd], b0.w, acc[i][3]);
            }
            if (CPT == 8) {
                float4 b1 = __ldg(B4 + 16 + tx);
#pragma unroll
                for (int i = 0; i < 4; i++) {
                    acc[i][4] = fmaf(a[i][dd], b1.x, acc[i][4]);
                    acc[i][5] = fmaf(a[i][dd], b1.y, acc[i][5]);
                    acc[i][6] = fmaf(a[i][dd], b1.z, acc[i][6]);
                    acc[i][7] = fmaf(a[i][dd], b1.w, acc[i][7]);
                }
            }
        }
    }
}

// ---------------------------------------------------------------------------
// Setup: Wq2[d, h*8+j] = sum_i Wq[d, h*8+i] * Wdot[i,j];  Wang^T transposes.
// ---------------------------------------------------------------------------
__global__ void setup_kernel(const float* __restrict__ Wq,
                             const float* __restrict__ Wdot,
                             const float* __restrict__ Wang_k,
                             const float* __restrict__ Wang_v) {
    int t = threadIdx.x;
    for (int o = t; o < 128 * 64; o += 256) {
        int d = o >> 6, hj = o & 63, h = hj >> 3, j = hj & 7;
        float s = 0.f;
#pragma unroll
        for (int i = 0; i < 8; ++i)
            s = fmaf(Wq[d * 64 + h * 8 + i], Wdot[i * 8 + j], s);
        g_Wq2[o] = s;
    }
    for (int o = t; o < 16 * 128; o += 256) {
        int s_ = o >> 7, d = o & 127;
        g_WangkT[o] = Wang_k[d * 16 + s_];
        g_WangvT[o] = Wang_v[d * 16 + s_];
    }
}

// ---------------------------------------------------------------------------
// q2 = node_attr @ Wq2   [n,128]@[128,64]
// ---------------------------------------------------------------------------
__global__ void __launch_bounds__(256) q2_kernel(const float* __restrict__ na, int n) {
    __shared__ float As[64 * 132];
    const int t = threadIdx.x, ty = t >> 4, tx = t & 15;
    const int n0 = blockIdx.x * 64;
    {
        const int r = t >> 2, seg = t & 3;
        const int nn = n0 + r;
#pragma unroll
        for (int q = 0; q < 8; q++) {
            const int d = seg * 32 + q * 4;
            float4 v = make_float4(0.f, 0.f, 0.f, 0.f);
            if (nn < n) v = __ldg((const float4*)(na + (size_t)nn * 128 + d));
            *(float4*)(As + r * 132 + d) = v;
        }
    }
    __syncthreads();
    float acc[4][4];
    gemm_core<128, 132, 4>(As, g_Wq2, acc, ty, tx);
#pragma unroll
    for (int i = 0; i < 4; i++) {
        const int nn = n0 + 4 * ty + i;
        if (nn < n)
            *(float4*)(g_q2 + (size_t)nn * 64 + tx * 4) =
                make_float4(acc[i][0], acc[i][1], acc[i][2], acc[i][3]);
    }
}

// ---------------------------------------------------------------------------
// Edge staging (stride-20 rows), 256 threads: 64 edges x 4 parts.
// ---------------------------------------------------------------------------
__device__ __forceinline__ void stage_edges(float* sm_ea, float* sm_sh, int* idx,
                                            const float* __restrict__ ea,
                                            const float* __restrict__ shp,
                                            int e0, int E, int t) {
    if (t < 64) {
        const int ge = e0 + t;
        int s = 0, d_ = 0;
        if (ge < E) { s = g_eidx[ge]; d_ = g_eidx[E + ge]; }
        idx[t] = s;
        idx[64 + t] = d_;
    }
    const int e = t >> 2, part = t & 3;
    const int ge = e0 + e;
    float4 va = make_float4(0.f, 0.f, 0.f, 0.f), vs = va;
    if (ge < E) {
        va = __ldg((const float4*)(ea + (size_t)ge * 16) + part);
        vs = __ldg((const float4*)(shp + (size_t)ge * 16) + part);
    }
    *(float4*)(sm_ea + e * 20 + part * 4) = va;
    *(float4*)(sm_sh + e * 20 + part * 4) = vs;
}

// ---------------------------------------------------------------------------
// K-pass: 64 edges/block, 256 threads. smem = 15488 floats = 60.5KB -> 3 CTAs.
// layout: EA[64x20] (EAL overlays) SH[64x20] G[64x132] H[64x68] idx[128].
// phases: stage | H | {XGk->G, Rk->regs} | big GEMM + alpha | scatter
// (unchanged from R13)
// ---------------------------------------------------------------------------
#define K_EA  0
#define K_SH  (64 * 20)
#define K_G   (2 * 64 * 20)
#define K_H   (K_G + 64 * 132)
#define K_IDX (K_H + 64 * 68)
#define K_SMEM (K_IDX + 128)
#define K_EAL K_EA

__global__ void __launch_bounds__(256, 3) edgek_kernel(
    const float* __restrict__ na, const float* __restrict__ ea,
    const float* __restrict__ shp,
    const float* __restrict__ Wlin_k, const float* __restrict__ W1k,
    const float* __restrict__ b1k, const float* __restrict__ W2k,
    int E) {
    extern __shared__ float sm[];
    int* idx = (int*)(sm + K_IDX);
    const int t = threadIdx.x;
    int ty, tx; thread_mapE(t, ty, tx);
    const int e0 = blockIdx.x * 64;

    stage_edges(sm + K_EA, sm + K_SH, idx, ea, shp, e0, E, t);
    __syncthreads();

    // Hk = relu(EA@W1k + b1k) -> dedicated H buffer (stride 68)
    {
        float acc[4][4];
        gemmE<16, 20, 4>(sm + K_EA, W1k, acc, ty, tx);
        float4 bk = __ldg((const float4*)(b1k) + tx);
#pragma unroll
        for (int i = 0; i < 4; i++)
            *(float4*)(sm + K_H + (16 * i + ty) * 68 + tx * 4) =
                make_float4(fmaxf(acc[i][0] + bk.x, 0.f), fmaxf(acc[i][1] + bk.y, 0.f),
                            fmaxf(acc[i][2] + bk.z, 0.f), fmaxf(acc[i][3] + bk.w, 0.f));
    }
    __syncthreads();

    // XGk = x_src * (SH @ Wang_k^T) -> G; then Rk = H @ W2k -> regs
    {
        float acc[4][8];
        gemmE<16, 20, 8>(sm + K_SH, g_WangkT, acc, ty, tx);
#pragma unroll
        for (int i = 0; i < 4; i++) {
            const int r = 16 * i + ty;
            const float* xb = na + (size_t)idx[r] * 128;
            float4 x0 = __ldg((const float4*)(xb + tx * 4));
            float4 x1 = __ldg((const float4*)(xb + 64 + tx * 4));
            *(float4*)(sm + K_G + r * 132 + tx * 4) =
                make_float4(acc[i][0] * x0.x, acc[i][1] * x0.y,
                            acc[i][2] * x0.z, acc[i][3] * x0.w);
            *(float4*)(sm + K_G + r * 132 + 64 + tx * 4) =
                make_float4(acc[i][4] * x1.x, acc[i][5] * x1.y,
                            acc[i][6] * x1.z, acc[i][7] * x1.w);
        }
    }
    float rk[4][4];
    gemmE<64, 68, 4>(sm + K_H, W2k, rk, ty, tx);
    __syncthreads();

    // K = (XGk @ Wlin_k) * Rk; alpha = <q2[dst], K> per head; ealpha -> EAL
    {
        float acc[4][4];
        gemmE<128, 132, 4>(sm + K_G, Wlin_k, acc, ty, tx);
#pragma unroll
        for (int i = 0; i < 4; i++) {
            const int r = 16 * i + ty;
            float4 q2v = __ldg((const float4*)(g_q2 + (size_t)idx[64 + r] * 64 + tx * 4));
            float p = acc[i][0] * rk[i][0] * q2v.x + acc[i][1] * rk[i][1] * q2v.y +
                      acc[i][2] * rk[i][2] * q2v.z + acc[i][3] * rk[i][3] * q2v.w;
            p += __shfl_xor_sync(0xffffffffu, p, 1);   // lane bit0 == tx bit0
            if ((tx & 1) == 0) sm[K_EAL + r * 8 + (tx >> 1)] = __expf(p);
        }
    }
    __syncthreads();

    // ealpha -> global; denominator scatter
    if (t < 128) {
        const int e = t >> 1, half = t & 1;
        if (e0 + e < E) {
            float4 v = *(float4*)(sm + K_EAL + e * 8 + half * 4);
            *(float4*)(g_ealpha + (size_t)(e0 + e) * 8 + half * 4) = v;
            red_add_v4(g_denom + (size_t)idx[64 + e] * 8 + half * 4, v);
        }
    }
}

// ---------------------------------------------------------------------------
// V-pass (R14): 64 edges/block, 256 threads. smem = 60.5KB -> 3 CTAs.
// launch_bounds(256,3); acc and rv never co-live:
//   stage | H | {XGv->G, EAL} | big GEMM acc | sync |
//   spill acc->G (dead) | rv = H@W2v | read V back (same thread) | scatter
// ---------------------------------------------------------------------------
#define V_EA  0
#define V_SH  (64 * 20)
#define V_G   (2 * 64 * 20)
#define V_H   (V_G + 64 * 132)
#define V_IDX (V_H + 64 * 68)
#define V_SMEM (V_IDX + 128)
#define V_EAL V_EA

__global__ void __launch_bounds__(256, 3) edgev_kernel(
    const float* __restrict__ na, const float* __restrict__ ea,
    const float* __restrict__ shp,
    const float* __restrict__ Wlin_v, const float* __restrict__ W1v,
    const float* __restrict__ b1v, const float* __restrict__ W2v,
    int E) {
    extern __shared__ float sm[];
    int* idx = (int*)(sm + V_IDX);
    const int t = threadIdx.x;
    int ty, tx; thread_mapE(t, ty, tx);
    const int e0 = blockIdx.x * 64;

    stage_edges(sm + V_EA, sm + V_SH, idx, ea, shp, e0, E, t);
    __syncthreads();

    // Hv = relu(EA@W1v + b1v) -> dedicated H buffer (stride 68)
    {
        float acc[4][4];
        gemmE<16, 20, 4>(sm + V_EA, W1v, acc, ty, tx);
        float4 bv = __ldg((const float4*)(b1v) + tx);
#pragma unroll
        for (int i = 0; i < 4; i++)
            *(float4*)(sm + V_H + (16 * i + ty) * 68 + tx * 4) =
                make_float4(fmaxf(acc[i][0] + bv.x, 0.f), fmaxf(acc[i][1] + bv.y, 0.f),
                            fmaxf(acc[i][2] + bv.z, 0.f), fmaxf(acc[i][3] + bv.w, 0.f));
    }
    __syncthreads();

    // XGv = x_src * (SH @ Wang_v^T) -> G; stage EAL (EA dead)
    {
        float acc[4][8];
        gemmE<16, 20, 8>(sm + V_SH, g_WangvT, acc, ty, tx);
#pragma unroll
        for (int i = 0; i < 4; i++) {
            const int r = 16 * i + ty;
            const float* xb = na + (size_t)idx[r] * 128;
            float4 x0 = __ldg((const float4*)(xb + tx * 4));
            float4 x1 = __ldg((const float4*)(xb + 64 + tx * 4));
            *(float4*)(sm + V_G + r * 132 + tx * 4) =
                make_float4(acc[i][0] * x0.x, acc[i][1] * x0.y,
                            acc[i][2] * x0.z, acc[i][3] * x0.w);
            *(float4*)(sm + V_G + r * 132 + 64 + tx * 4) =
                make_float4(acc[i][4] * x1.x, acc[i][5] * x1.y,
                            acc[i][6] * x1.z, acc[i][7] * x1.w);
        }
    }
    if (t < 128) {
        const int e = t >> 1, half = t & 1;
        float4 v = make_float4(0.f, 0.f, 0.f, 0.f);
        if (e0 + e < E)
            v = __ldg((const float4*)(g_ealpha + (size_t)(e0 + e) * 8) + half);
        *(float4*)(sm + V_EAL + e * 8 + half * 4) = v;
    }
    __syncthreads();

    // big GEMM: acc = XGv @ Wlin_v  (rv NOT live here)
    {
        float acc[4][8];
        gemmE<128, 132, 8>(sm + V_G, Wlin_v, acc, ty, tx);
        __syncthreads();   // all reads of G complete before overwrite

        // spill acc into G at this thread's own output slots
#pragma unroll
        for (int i = 0; i < 4; i++) {
            const int r = 16 * i + ty;
            *(float4*)(sm + V_G + r * 132 + tx * 4) =
                make_float4(acc[i][0], acc[i][1], acc[i][2], acc[i][3]);
            *(float4*)(sm + V_G + r * 132 + 64 + tx * 4) =
                make_float4(acc[i][4], acc[i][5], acc[i][6], acc[i][7]);
        }
    }

    // rv = H @ W2v (acc regs recycled; H intact)
    float rv[4][8];
    gemmE<64, 68, 8>(sm + V_H, W2v, rv, ty, tx);

    // read V back (same thread wrote it -> no sync), scale, scatter
    {
        const int h0 = tx >> 2, h1 = 4 + (tx >> 2);   // warp-uniform heads
#pragma unroll
        for (int i = 0; i < 4; i++) {
            const int r = 16 * i + ty;
            if (e0 + r < E) {
                const float eh0 = sm[V_EAL + r * 8 + h0];
                const float eh1 = sm[V_EAL + r * 8 + h1];
                float4 v0 = *(const float4*)(sm + V_G + r * 132 + tx * 4);
                float4 v1 = *(const float4*)(sm + V_G + r * 132 + 64 + tx * 4);
                float* np = g_numer + (size_t)idx[64 + r] * 128;
                red_add_v4(np + tx * 4,
                           make_float4(v0.x * rv[i][0] * eh0, v0.y * rv[i][1] * eh0,
                                       v0.z * rv[i][2] * eh0, v0.w * rv[i][3] * eh0));
                red_add_v4(np + 64 + tx * 4,
                           make_float4(v1.x * rv[i][4] * eh1, v1.y * rv[i][5] * eh1,
                                       v1.z * rv[i][6] * eh1, v1.w * rv[i][7] * eh1));
            }
        }
    }
}

// ---------------------------------------------------------------------------
// out = (numer / denom per head) @ Wout
// ---------------------------------------------------------------------------
__global__ void __launch_bounds__(256) out_kernel(const float* __restrict__ Wout,
                                                  float* __restrict__ out, int n) {
    __shared__ float As[64 * 132];
    const int t = threadIdx.x, ty = t >> 4, tx = t & 15;
    const int n0 = blockIdx.x * 64;
    {
        const int r = t >> 2, seg = t & 3;
        const int nn = n0 + r;
#pragma unroll
        for (int q = 0; q < 8; q++) {
            const int d = seg * 32 + 4 * q;
            float4 v = make_float4(0.f, 0.f, 0.f, 0.f);
            if (nn < n) {
                v = *(const float4*)(g_numer + (size_t)nn * 128 + d);
                float den = g_denom[(size_t)nn * 8 + (d >> 4)];
                float inv = (den > 0.f) ? __frcp_rn(den) : 0.f;
                v.x *= inv; v.y *= inv; v.z *= inv; v.w *= inv;
            }
            *(float4*)(As + r * 132 + d) = v;
        }
    }
    __syncthreads();
    float acc[4][8];
    gemm_core<128, 132, 8>(As, Wout, acc, ty, tx);
#pragma unroll
    for (int i = 0; i < 4; i++) {
        const int m = n0 + 4 * ty + i;
        if (m < n) {
            *(float4*)(out + (size_t)m * 128 + tx * 4) =
                make_float4(acc[i][0], acc[i][1], acc[i][2], acc[i][3]);
            *(float4*)(out + (size_t)m * 128 + 64 + tx * 4) =
                make_float4(acc[i][4], acc[i][5], acc[i][6], acc[i][7]);
        }
    }
}

// ---------------------------------------------------------------------------
extern "C" void kernel_launch(void* const* d_in, const int* in_sizes, int n_in,
                              void* d_out, int out_size) {
    const float* na      = (const float*)d_in[0];
    const float* ea      = (const float*)d_in[1];
    const float* shp     = (const float*)d_in[2];
    const float* Wq      = (const float*)d_in[3];
    const float* Wang_k  = (const float*)d_in[4];
    const float* Wlin_k  = (const float*)d_in[5];
    const float* W1k     = (const float*)d_in[6];
    const float* b1k     = (const float*)d_in[7];
    const float* W2k     = (const float*)d_in[8];
    const float* Wang_v  = (const float*)d_in[9];
    const float* Wlin_v  = (const float*)d_in[10];
    const float* W1v     = (const float*)d_in[11];
    const float* b1v     = (const float*)d_in[12];
    const float* W2v     = (const float*)d_in[13];
    const float* Wdot    = (const float*)d_in[14];
    const float* Wout    = (const float*)d_in[15];
    const void*  eidx    = d_in[16];

    const int n = in_sizes[0] / 128;
    const int E = in_sizes[1] / 16;
    const int twoE = 2 * E;

    void *dden = nullptr, *dnum = nullptr;
    cudaGetSymbolAddress(&dden, g_denom);
    cudaGetSymbolAddress(&dnum, g_numer);
    cudaMemsetAsync(dden, 0, (size_t)n * 8 * sizeof(float), 0);   // launch 1
    cudaMemsetAsync(dnum, 0, (size_t)n * 128 * sizeof(float), 0); // launch 2

    convert_idx_kernel<<<(twoE + 255) / 256, 256>>>(eidx, twoE);  // launch 3
    setup_kernel<<<1, 256>>>(Wq, Wdot, Wang_k, Wang_v);           // launch 4

    const int nb = (n + 63) / 64;
    q2_kernel<<<nb, 256>>>(na, n);                                // launch 5

    const int eb = (E + 63) / 64;
    cudaFuncSetAttribute(edgek_kernel, cudaFuncAttributeMaxDynamicSharedMemorySize,
                         (int)(K_SMEM * sizeof(float)));
    edgek_kernel<<<eb, 256, K_SMEM * sizeof(float)>>>(            // launch 6 (profiled)
        na, ea, shp, Wlin_k, W1k, b1k, W2k, E);

    cudaFuncSetAttribute(edgev_kernel, cudaFuncAttributeMaxDynamicSharedMemorySize,
                         (int)(V_SMEM * sizeof(float)));
    edgev_kernel<<<eb, 256, V_SMEM * sizeof(float)>>>(            // launch 7
        na, ea, shp, Wlin_v, W1v, b1v, W2v, E);

    out_kernel<<<nb, 256>>>(Wout, (float*)d_out, n);              // launch 8
}

// round 15
// speedup vs baseline: 1.0290x; 1.0290x over previous
#include <cuda_runtime.h>
#include <cstdint>
#include <cstddef>

// ---------------------------------------------------------------------------
// MultiheadAttention (equivariant graph attention), fp32, round 15.
// N=50000 nodes, E=800000 edges, D_IN=128, SH=16, EA=16, H=8, DQ=DK=64, DV=128
//
// R15 = composition of measured-best pieces + instrumentation shift:
//  * edgek: R13/R14 form (638us best; dedicated H, 4 syncs, 3 CTAs).
//  * edgev: EXACT R11 form (only edgev in the 1755us best; (256,2),
//    43.5KB, registerized rv). R12/R13/R14 blind restructures all lost.
//  * two memsets replaced by one zero_kernel -> edgev becomes launch #6,
//    i.e. THE PROFILED LAUNCH (edgev has never been profiled; it's ~990us).
// ---------------------------------------------------------------------------

#define NMAX 50000
#define EMAX 800000

__device__ float g_q2[NMAX * 64];
__device__ float g_Wq2[128 * 64];
__device__ float g_WangkT[16 * 128];
__device__ float g_WangvT[16 * 128];
__device__ float g_denom[NMAX * 8];
__device__ float g_numer[NMAX * 128];
__device__ float g_ealpha[EMAX * 8];
__device__ int   g_eidx[2 * EMAX];

__device__ __forceinline__ void red_add_v4(float* p, float4 v) {
    asm volatile("red.global.add.v4.f32 [%0], {%1,%2,%3,%4};"
                 :: "l"(p), "f"(v.x), "f"(v.y), "f"(v.z), "f"(v.w)
                 : "memory");
}

// Edge-kernel map: 256 threads -> 16 ty x 16 tx; warp = 8 ty x 4 tx.
// lane bit0 == tx bit0 (alpha shfl pairing). Rows owned: r = 16*i + ty.
__device__ __forceinline__ void thread_mapE(int t, int& ty, int& tx) {
    const int lane = t & 31, w = t >> 5;
    tx = ((w & 3) << 2) | (lane & 3);
    ty = ((w >> 2) << 3) | (lane >> 2);
}

// ---------------------------------------------------------------------------
// Zero both accumulator tables in ONE launch (shifts edgev to ncu slot 6).
// ---------------------------------------------------------------------------
__global__ void zero_kernel(int n) {
    const float4 z = make_float4(0.f, 0.f, 0.f, 0.f);
    const int i = blockIdx.x * blockDim.x + threadIdx.x;
    const int nd = n * 2;        // n*8 floats = n*2 float4
    if (i < nd) reinterpret_cast<float4*>(g_denom)[i] = z;
    const int nn = n * 32;       // n*128 floats = n*32 float4
    for (int j = i; j < nn; j += gridDim.x * blockDim.x)
        reinterpret_cast<float4*>(g_numer)[j] = z;
}

// ---------------------------------------------------------------------------
// Index dtype detection + normalization (int32 or int64 input).
// ---------------------------------------------------------------------------
__global__ void convert_idx_kernel(const void* __restrict__ p, int twoE) {
    const int* pi = (const int*)p;
    int w = 2 * (int)threadIdx.x + 1;
    int nz = (w < twoE) ? (pi[w] != 0) : 0;
    __shared__ int any;
    if (threadIdx.x == 0) any = 0;
    __syncthreads();
    if (nz) any = 1;
    __syncthreads();
    const bool is64 = (any == 0);
    const int i = blockIdx.x * blockDim.x + threadIdx.x;
    if (i < twoE) {
        long long v = is64 ? __ldg((const long long*)p + i)
                           : (long long)__ldg((const int*)p + i);
        g_eidx[i] = (int)v;
    }
}

// ---------------------------------------------------------------------------
// Edge GEMM core (interleaved rows r=16i+ty): C[64,16*CPT] = A[64,KD]@B
// A in smem, LDA must be 4*odd mod 32 (20/68/132). B via __ldg, 64B/warp.
// ---------------------------------------------------------------------------
template <int KD, int LDA, int CPT>
__device__ __forceinline__ void gemmE(const float* __restrict__ As,
                                      const float* __restrict__ Bg,
                                      float (&acc)[4][CPT], int ty, int tx) {
    constexpr int NO = 16 * CPT;
#pragma unroll
    for (int i = 0; i < 4; i++)
#pragma unroll
        for (int j = 0; j < CPT; j++) acc[i][j] = 0.f;

#pragma unroll
    for (int d = 0; d < KD; d += 4) {
        float a[4][4];
#pragma unroll
        for (int i = 0; i < 4; i++)
            *(float4*)&a[i][0] = *(const float4*)(As + (16 * i + ty) * LDA + d);
#pragma unroll
        for (int dd = 0; dd < 4; ++dd) {
            const float4* B4 = reinterpret_cast<const float4*>(Bg + (size_t)(d + dd) * NO);
            float4 b0 = __ldg(B4 + tx);
#pragma unroll
            for (int i = 0; i < 4; i++) {
                acc[i][0] = fmaf(a[i][dd], b0.x, acc[i][0]);
                acc[i][1] = fmaf(a[i][dd], b0.y, acc[i][1]);
                acc[i][2] = fmaf(a[i][dd], b0.z, acc[i][2]);
                acc[i][3] = fmaf(a[i][dd], b0.w, acc[i][3]);
            }
            if (CPT == 8) {
                float4 b1 = __ldg(B4 + 16 + tx);
#pragma unroll
                for (int i = 0; i < 4; i++) {
                    acc[i][4] = fmaf(a[i][dd], b1.x, acc[i][4]);
                    acc[i][5] = fmaf(a[i][dd], b1.y, acc[i][5]);
                    acc[i][6] = fmaf(a[i][dd], b1.z, acc[i][6]);
                    acc[i][7] = fmaf(a[i][dd], b1.w, acc[i][7]);
                }
            }
        }
    }
}

// R6-style core for q2/out kernels (rows 4ty+i, ty = t>>4).
template <int KD, int LDA, int CPT>
__device__ __forceinline__ void gemm_core(const float* __restrict__ As,
                                          const float* __restrict__ Bg,
                                          float (&acc)[4][CPT], int ty, int tx) {
    constexpr int NO = 16 * CPT;
#pragma unroll
    for (int i = 0; i < 4; i++)
#pragma unroll
        for (int j = 0; j < CPT; j++) acc[i][j] = 0.f;

#pragma unroll
    for (int d = 0; d < KD; d += 4) {
        float a[4][4];
#pragma unroll
        for (int i = 0; i < 4; i++)
            *(float4*)&a[i][0] = *(const float4*)(As + (4 * ty + i) * LDA + d);
#pragma unroll
        for (int dd = 0; dd < 4; ++dd) {
            const float4* B4 = reinterpret_cast<const float4*>(Bg + (size_t)(d + dd) * NO);
            float4 b0 = __ldg(B4 + tx);
#pragma unroll
            for (int i = 0; i < 4; i++) {
                acc[i][0] = fmaf(a[i][dd], b0.x, acc[i][0]);
                acc[i][1] = fmaf(a[i][dd], b0.y, acc[i][1]);
                acc[i][2] = fmaf(a[i][dd], b0.z, acc[i][2]);
                acc[i][3] = fmaf(a[i][dd], b0.w, acc[i][3]);
            }
            if (CPT == 8) {
                float4 b1 = __ldg(B4 + 16 + tx);
#pragma unroll
                for (int i = 0; i < 4; i++) {
                    acc[i][4] = fmaf(a[i][dd], b1.x, acc[i][4]);
                    acc[i][5] = fmaf(a[i][dd], b1.y, acc[i][5]);
                    acc[i][6] = fmaf(a[i][dd], b1.z, acc[i][6]);
                    acc[i][7] = fmaf(a[i][dd], b1.w, acc[i][7]);
                }
            }
        }
    }
}

// ---------------------------------------------------------------------------
// Setup: Wq2[d, h*8+j] = sum_i Wq[d, h*8+i] * Wdot[i,j];  Wang^T transposes.
// ---------------------------------------------------------------------------
__global__ void setup_kernel(const float* __restrict__ Wq,
                             const float* __restrict__ Wdot,
                             const float* __restrict__ Wang_k,
                             const float* __restrict__ Wang_v) {
    int t = threadIdx.x;
    for (int o = t; o < 128 * 64; o += 256) {
        int d = o >> 6, hj = o & 63, h = hj >> 3, j = hj & 7;
        float s = 0.f;
#pragma unroll
        for (int i = 0; i < 8; ++i)
            s = fmaf(Wq[d * 64 + h * 8 + i], Wdot[i * 8 + j], s);
        g_Wq2[o] = s;
    }
    for (int o = t; o < 16 * 128; o += 256) {
        int s_ = o >> 7, d = o & 127;
        g_WangkT[o] = Wang_k[d * 16 + s_];
        g_WangvT[o] = Wang_v[d * 16 + s_];
    }
}

// ---------------------------------------------------------------------------
// q2 = node_attr @ Wq2   [n,128]@[128,64]
// ---------------------------------------------------------------------------
__global__ void __launch_bounds__(256) q2_kernel(const float* __restrict__ na, int n) {
    __shared__ float As[64 * 132];
    const int t = threadIdx.x, ty = t >> 4, tx = t & 15;
    const int n0 = blockIdx.x * 64;
    {
        const int r = t >> 2, seg = t & 3;
        const int nn = n0 + r;
#pragma unroll
        for (int q = 0; q < 8; q++) {
            const int d = seg * 32 + q * 4;
            float4 v = make_float4(0.f, 0.f, 0.f, 0.f);
            if (nn < n) v = __ldg((const float4*)(na + (size_t)nn * 128 + d));
            *(float4*)(As + r * 132 + d) = v;
        }
    }
    __syncthreads();
    float acc[4][4];
    gemm_core<128, 132, 4>(As, g_Wq2, acc, ty, tx);
#pragma unroll
    for (int i = 0; i < 4; i++) {
        const int nn = n0 + 4 * ty + i;
        if (nn < n)
            *(float4*)(g_q2 + (size_t)nn * 64 + tx * 4) =
                make_float4(acc[i][0], acc[i][1], acc[i][2], acc[i][3]);
    }
}

// ---------------------------------------------------------------------------
// Edge staging (stride-20 rows), 256 threads: 64 edges x 4 parts.
// ---------------------------------------------------------------------------
__device__ __forceinline__ void stage_edges(float* sm_ea, float* sm_sh, int* idx,
                                            const float* __restrict__ ea,
                                            const float* __restrict__ shp,
                                            int e0, int E, int t) {
    if (t < 64) {
        const int ge = e0 + t;
        int s = 0, d_ = 0;
        if (ge < E) { s = g_eidx[ge]; d_ = g_eidx[E + ge]; }
        idx[t] = s;
        idx[64 + t] = d_;
    }
    const int e = t >> 2, part = t & 3;
    const int ge = e0 + e;
    float4 va = make_float4(0.f, 0.f, 0.f, 0.f), vs = va;
    if (ge < E) {
        va = __ldg((const float4*)(ea + (size_t)ge * 16) + part);
        vs = __ldg((const float4*)(shp + (size_t)ge * 16) + part);
    }
    *(float4*)(sm_ea + e * 20 + part * 4) = va;
    *(float4*)(sm_sh + e * 20 + part * 4) = vs;
}

// ---------------------------------------------------------------------------
// K-pass (R13 form, 638us): 64 edges/block, 256 threads. smem = 60.5KB -> 3.
// layout: EA[64x20] (EAL overlays) SH[64x20] G[64x132] H[64x68] idx[128].
// phases: stage | H | {XGk->G, Rk->regs} | big GEMM + alpha | scatter
// ---------------------------------------------------------------------------
#define K_EA  0
#define K_SH  (64 * 20)
#define K_G   (2 * 64 * 20)
#define K_H   (K_G + 64 * 132)
#define K_IDX (K_H + 64 * 68)
#define K_SMEM (K_IDX + 128)
#define K_EAL K_EA

__global__ void __launch_bounds__(256, 3) edgek_kernel(
    const float* __restrict__ na, const float* __restrict__ ea,
    const float* __restrict__ shp,
    const float* __restrict__ Wlin_k, const float* __restrict__ W1k,
    const float* __restrict__ b1k, const float* __restrict__ W2k,
    int E) {
    extern __shared__ float sm[];
    int* idx = (int*)(sm + K_IDX);
    const int t = threadIdx.x;
    int ty, tx; thread_mapE(t, ty, tx);
    const int e0 = blockIdx.x * 64;

    stage_edges(sm + K_EA, sm + K_SH, idx, ea, shp, e0, E, t);
    __syncthreads();

    // Hk = relu(EA@W1k + b1k) -> dedicated H buffer (stride 68)
    {
        float acc[4][4];
        gemmE<16, 20, 4>(sm + K_EA, W1k, acc, ty, tx);
        float4 bk = __ldg((const float4*)(b1k) + tx);
#pragma unroll
        for (int i = 0; i < 4; i++)
            *(float4*)(sm + K_H + (16 * i + ty) * 68 + tx * 4) =
                make_float4(fmaxf(acc[i][0] + bk.x, 0.f), fmaxf(acc[i][1] + bk.y, 0.f),
                            fmaxf(acc[i][2] + bk.z, 0.f), fmaxf(acc[i][3] + bk.w, 0.f));
    }
    __syncthreads();

    // XGk = x_src * (SH @ Wang_k^T) -> G; then Rk = H @ W2k -> regs
    {
        float acc[4][8];
        gemmE<16, 20, 8>(sm + K_SH, g_WangkT, acc, ty, tx);
#pragma unroll
        for (int i = 0; i < 4; i++) {
            const int r = 16 * i + ty;
            const float* xb = na + (size_t)idx[r] * 128;
            float4 x0 = __ldg((const float4*)(xb + tx * 4));
            float4 x1 = __ldg((const float4*)(xb + 64 + tx * 4));
            *(float4*)(sm + K_G + r * 132 + tx * 4) =
                make_float4(acc[i][0] * x0.x, acc[i][1] * x0.y,
                            acc[i][2] * x0.z, acc[i][3] * x0.w);
            *(float4*)(sm + K_G + r * 132 + 64 + tx * 4) =
                make_float4(acc[i][4] * x1.x, acc[i][5] * x1.y,
                            acc[i][6] * x1.z, acc[i][7] * x1.w);
        }
    }
    float rk[4][4];
    gemmE<64, 68, 4>(sm + K_H, W2k, rk, ty, tx);
    __syncthreads();

    // K = (XGk @ Wlin_k) * Rk; alpha = <q2[dst], K> per head; ealpha -> EAL
    {
        float acc[4][4];
        gemmE<128, 132, 4>(sm + K_G, Wlin_k, acc, ty, tx);
#pragma unroll
        for (int i = 0; i < 4; i++) {
            const int r = 16 * i + ty;
            float4 q2v = __ldg((const float4*)(g_q2 + (size_t)idx[64 + r] * 64 + tx * 4));
            float p = acc[i][0] * rk[i][0] * q2v.x + acc[i][1] * rk[i][1] * q2v.y +
                      acc[i][2] * rk[i][2] * q2v.z + acc[i][3] * rk[i][3] * q2v.w;
            p += __shfl_xor_sync(0xffffffffu, p, 1);   // lane bit0 == tx bit0
            if ((tx & 1) == 0) sm[K_EAL + r * 8 + (tx >> 1)] = __expf(p);
        }
    }
    __syncthreads();

    // ealpha -> global; denominator scatter
    if (t < 128) {
        const int e = t >> 1, half = t & 1;
        if (e0 + e < E) {
            float4 v = *(float4*)(sm + K_EAL + e * 8 + half * 4);
            *(float4*)(g_ealpha + (size_t)(e0 + e) * 8 + half * 4) = v;
            red_add_v4(g_denom + (size_t)idx[64 + e] * 8 + half * 4, v);
        }
    }
}

// ---------------------------------------------------------------------------
// V-pass (EXACT R11 form): 64 edges/block, 256 threads. smem = 43.5KB.
// launch_bounds(256,2): reg cap 128 -> rv[4][8] registerized, no spills.
// layout: EA[64x20] (EAL overlays) SH[64x20] G[64x132] (H@68 -> XGv@132)
//         idx[128].  Rv lives in registers.
// ---------------------------------------------------------------------------
#define V_EA  0
#define V_SH  (64 * 20)
#define V_G   (2 * 64 * 20)
#define V_IDX (V_G + 64 * 132)
#define V_SMEM (V_IDX + 128)
#define V_EAL V_EA

__global__ void __launch_bounds__(256, 2) edgev_kernel(
    const float* __restrict__ na, const float* __restrict__ ea,
    const float* __restrict__ shp,
    const float* __restrict__ Wlin_v, const float* __restrict__ W1v,
    const float* __restrict__ b1v, const float* __restrict__ W2v,
    int E) {
    extern __shared__ float sm[];
    int* idx = (int*)(sm + V_IDX);
    const int t = threadIdx.x;
    int ty, tx; thread_mapE(t, ty, tx);
    const int e0 = blockIdx.x * 64;

    stage_edges(sm + V_EA, sm + V_SH, idx, ea, shp, e0, E, t);
    __syncthreads();

    // Hv = relu(EA@W1v + b1v) -> G (stride 68)
    {
        float acc[4][4];
        gemmE<16, 20, 4>(sm + V_EA, W1v, acc, ty, tx);
        float4 bv = __ldg((const float4*)(b1v) + tx);
#pragma unroll
        for (int i = 0; i < 4; i++)
            *(float4*)(sm + V_G + (16 * i + ty) * 68 + tx * 4) =
                make_float4(fmaxf(acc[i][0] + bv.x, 0.f), fmaxf(acc[i][1] + bv.y, 0.f),
                            fmaxf(acc[i][2] + bv.z, 0.f), fmaxf(acc[i][3] + bv.w, 0.f));
    }
    __syncthreads();

    // Rv = Hv @ W2v -> REGISTERS; stage ealpha into EAL (EA dead)
    float rv[4][8];
    gemmE<64, 68, 8>(sm + V_G, W2v, rv, ty, tx);
    if (t < 128) {
        const int e = t >> 1, half = t & 1;
        float4 v = make_float4(0.f, 0.f, 0.f, 0.f);
        if (e0 + e < E)
            v = __ldg((const float4*)(g_ealpha + (size_t)(e0 + e) * 8) + half);
        *(float4*)(sm + V_EAL + e * 8 + half * 4) = v;
    }
    __syncthreads();

    // XGv = x_src * (SH @ Wang_v^T), fused -> G (stride 132)
    {
        float acc[4][8];
        gemmE<16, 20, 8>(sm + V_SH, g_WangvT, acc, ty, tx);
#pragma unroll
        for (int i = 0; i < 4; i++) {
            const int r = 16 * i + ty;
            const float* xb = na + (size_t)idx[r] * 128;
            float4 x0 = __ldg((const float4*)(xb + tx * 4));
            float4 x1 = __ldg((const float4*)(xb + 64 + tx * 4));
            *(float4*)(sm + V_G + r * 132 + tx * 4) =
                make_float4(acc[i][0] * x0.x, acc[i][1] * x0.y,
                            acc[i][2] * x0.z, acc[i][3] * x0.w);
            *(float4*)(sm + V_G + r * 132 + 64 + tx * 4) =
                make_float4(acc[i][4] * x1.x, acc[i][5] * x1.y,
                            acc[i][6] * x1.z, acc[i][7] * x1.w);
        }
    }
    __syncthreads();

    // V = (XGv @ Wlin_v) * Rv; numer[dst] += ealpha[h] * V
    {
        float acc[4][8];
        gemmE<128, 132, 8>(sm + V_G, Wlin_v, acc, ty, tx);
        const int h0 = tx >> 2, h1 = 4 + (tx >> 2);   // warp-uniform heads
#pragma unroll
        for (int i = 0; i < 4; i++) {
            const int r = 16 * i + ty;
            if (e0 + r < E) {
                const float eh0 = sm[V_EAL + r * 8 + h0];
                const float eh1 = sm[V_EAL + r * 8 + h1];
                float* np = g_numer + (size_t)idx[64 + r] * 128;
                red_add_v4(np + tx * 4,
                           make_float4(acc[i][0] * rv[i][0] * eh0, acc[i][1] * rv[i][1] * eh0,
                                       acc[i][2] * rv[i][2] * eh0, acc[i][3] * rv[i][3] * eh0));
                red_add_v4(np + 64 + tx * 4,
                           make_float4(acc[i][4] * rv[i][4] * eh1, acc[i][5] * rv[i][5] * eh1,
                                       acc[i][6] * rv[i][6] * eh1, acc[i][7] * rv[i][7] * eh1));
            }
        }
    }
}

// ---------------------------------------------------------------------------
// out = (numer / denom per head) @ Wout
// ---------------------------------------------------------------------------
__global__ void __launch_bounds__(256) out_kernel(const float* __restrict__ Wout,
                                                  float* __restrict__ out, int n) {
    __shared__ float As[64 * 132];
    const int t = threadIdx.x, ty = t >> 4, tx = t & 15;
    const int n0 = blockIdx.x * 64;
    {
        const int r = t >> 2, seg = t & 3;
        const int nn = n0 + r;
#pragma unroll
        for (int q = 0; q < 8; q++) {
            const int d = seg * 32 + 4 * q;
            float4 v = make_float4(0.f, 0.f, 0.f, 0.f);
            if (nn < n) {
                v = *(const float4*)(g_numer + (size_t)nn * 128 + d);
                float den = g_denom[(size_t)nn * 8 + (d >> 4)];
                float inv = (den > 0.f) ? __frcp_rn(den) : 0.f;
                v.x *= inv; v.y *= inv; v.z *= inv; v.w *= inv;
            }
            *(float4*)(As + r * 132 + d) = v;
        }
    }
    __syncthreads();
    float acc[4][8];
    gemm_core<128, 132, 8>(As, Wout, acc, ty, tx);
#pragma unroll
    for (int i = 0; i < 4; i++) {
        const int m = n0 + 4 * ty + i;
        if (m < n) {
            *(float4*)(out + (size_t)m * 128 + tx * 4) =
                make_float4(acc[i][0], acc[i][1], acc[i][2], acc[i][3]);
            *(float4*)(out + (size_t)m * 128 + 64 + tx * 4) =
                make_float4(acc[i][4], acc[i][5], acc[i][6], acc[i][7]);
        }
    }
}

// ---------------------------------------------------------------------------
extern "C" void kernel_launch(void* const* d_in, const int* in_sizes, int n_in,
                              void* d_out, int out_size) {
    const float* na      = (const float*)d_in[0];
    const float* ea      = (const float*)d_in[1];
    const float* shp     = (const float*)d_in[2];
    const float* Wq      = (const float*)d_in[3];
    const float* Wang_k  = (const float*)d_in[4];
    const float* Wlin_k  = (const float*)d_in[5];
    const float* W1k     = (const float*)d_in[6];
    const float* b1k     = (const float*)d_in[7];
    const float* W2k     = (const float*)d_in[8];
    const float* Wang_v  = (const float*)d_in[9];
    const float* Wlin_v  = (const float*)d_in[10];
    const float* W1v     = (const float*)d_in[11];
    const float* b1v     = (const float*)d_in[12];
    const float* W2v     = (const float*)d_in[13];
    const float* Wdot    = (const float*)d_in[14];
    const float* Wout    = (const float*)d_in[15];
    const void*  eidx    = d_in[16];

    const int n = in_sizes[0] / 128;
    const int E = in_sizes[1] / 16;
    const int twoE = 2 * E;

    zero_kernel<<<(n * 32 + 255) / 256, 256>>>(n);                // launch 1

    convert_idx_kernel<<<(twoE + 255) / 256, 256>>>(eidx, twoE);  // launch 2
    setup_kernel<<<1, 256>>>(Wq, Wdot, Wang_k, Wang_v);           // launch 3

    const int nb = (n + 63) / 64;
    q2_kernel<<<nb, 256>>>(na, n);                                // launch 4

    const int eb = (E + 63) / 64;
    cudaFuncSetAttribute(edgek_kernel, cudaFuncAttributeMaxDynamicSharedMemorySize,
                         (int)(K_SMEM * sizeof(float)));
    edgek_kernel<<<eb, 256, K_SMEM * sizeof(float)>>>(            // launch 5
        na, ea, shp, Wlin_k, W1k, b1k, W2k, E);

    cudaFuncSetAttribute(edgev_kernel, cudaFuncAttributeMaxDynamicSharedMemorySize,
                         (int)(V_SMEM * sizeof(float)));
    edgev_kernel<<<eb, 256, V_SMEM * sizeof(float)>>>(            // launch 6 (profiled)
        na, ea, shp, Wlin_v, W1v, b1v, W2v, E);

    out_kernel<<<nb, 256>>>(Wout, (float*)d_out, n);              // launch 7
}